// round 5
// baseline (speedup 1.0000x reference)
#include <cuda_runtime.h>
#include <cuda_bf16.h>
#include <cstdint>
#include <cstddef>

// ---------------------------------------------------------------------------
// MinGRU: split-bf16 GEMM via mma.sync.m16n8k16 + cp.async pipeline.
// Correct 3-term split (R4 bug: [hi|lo]x[hi|lo] K-concat only gives the
// DIAGONAL products hi.hi + lo.lo, dropping the cross terms -> bf16-level
// error 2.9e-3). Now per-chunk source indirection gives
//   x_hi.w_hi + x_lo.w_hi + x_hi.w_lo   (only lo.lo ~4e-6 dropped)
// at 1.5x base bf16 MMA cost. Then bias/sigmoid epilogue + affine scan.
// ---------------------------------------------------------------------------

#define B_DIM 16
#define T_DIM 2048
#define D_DIM 1024
#define H_DIM 1024
#define M_TOT (B_DIM * T_DIM)   // 32768
#define N_TOT (2 * H_DIM)       // 2048
#define K2    (2 * D_DIM)       // 2048 (hi | lo halves)

#define KC      64              // K elems per pipeline chunk (128B rows)
#define NSTG    3
#define NCHUNK  48              // 16 hi.hi + 16 lo.hi + 16 hi.lo
#define TILE_B  (128 * 128)     // 16KB: 128 rows x 128 bytes
#define STG_B   (2 * TILE_B)    // A tile + B tile per stage = 32KB
#define SMEM_TOTAL (NSTG * STG_B)  // 98304

// ---------------- scratch (static device memory; no allocation) -------------
__device__ __align__(256) __nv_bfloat16 g_x2[(size_t)M_TOT * K2];   // 128MB [hi|lo]
__device__ __align__(256) __nv_bfloat16 g_w2[(size_t)N_TOT * K2];   // 8MB  [hi|lo]
__device__ __align__(256) float g_zb[(size_t)M_TOT * H_DIM];        // gates
__device__ __align__(256) float g_hb[(size_t)M_TOT * H_DIM];        // candidates

// ---------------- PTX helpers ----------------------------------------------
__device__ __forceinline__ uint32_t s2u(const void* p) {
    return (uint32_t)__cvta_generic_to_shared(p);
}
__device__ __forceinline__ void cp_async16(uint32_t dst, const void* src) {
    asm volatile("cp.async.cg.shared.global [%0], [%1], 16;" :: "r"(dst), "l"(src) : "memory");
}
__device__ __forceinline__ void cp_commit() {
    asm volatile("cp.async.commit_group;" ::: "memory");
}
__device__ __forceinline__ void cp_wait1() {
    asm volatile("cp.async.wait_group 1;" ::: "memory");
}
__device__ __forceinline__ void ldsm4(uint32_t* r, uint32_t addr) {
    asm volatile("ldmatrix.sync.aligned.m8n8.x4.shared.b16 {%0,%1,%2,%3}, [%4];"
                 : "=r"(r[0]), "=r"(r[1]), "=r"(r[2]), "=r"(r[3]) : "r"(addr));
}
__device__ __forceinline__ void mma16816(float* d, const uint32_t* a, uint32_t b0, uint32_t b1) {
    asm volatile("mma.sync.aligned.m16n8k16.row.col.f32.bf16.bf16.f32 "
                 "{%0,%1,%2,%3}, {%4,%5,%6,%7}, {%8,%9}, {%0,%1,%2,%3};"
                 : "+f"(d[0]), "+f"(d[1]), "+f"(d[2]), "+f"(d[3])
                 : "r"(a[0]), "r"(a[1]), "r"(a[2]), "r"(a[3]), "r"(b0), "r"(b1));
}

// ---------------- split kernels ---------------------------------------------
__global__ void split_x_k(const float* __restrict__ x) {
    size_t i = (size_t)blockIdx.x * blockDim.x + threadIdx.x;  // group of 8 elems
    size_t e = i * 8;
    size_t row = e >> 10;
    int k = (int)(e & 1023);
    const float4* src = (const float4*)(x + e);
    float4 a = src[0], b = src[1];
    float f[8] = {a.x, a.y, a.z, a.w, b.x, b.y, b.z, b.w};
    union { __nv_bfloat16 h[8]; uint4 u; } H, L;
#pragma unroll
    for (int j = 0; j < 8; j++) {
        __nv_bfloat16 hi = __float2bfloat16(f[j]);
        H.h[j] = hi;
        L.h[j] = __float2bfloat16(f[j] - __bfloat162float(hi));
    }
    __nv_bfloat16* dst = g_x2 + row * K2 + k;
    *(uint4*)dst = H.u;
    *(uint4*)(dst + 1024) = L.u;
}

__global__ void split_w_k(const float* __restrict__ Wz, const float* __restrict__ Wh) {
    size_t i = (size_t)blockIdx.x * blockDim.x + threadIdx.x;
    size_t e = i * 8;
    int row = (int)(e >> 10);
    int k = (int)(e & 1023);
    const float* srcp = (row < H_DIM) ? (Wz + (size_t)row * D_DIM + k)
                                      : (Wh + (size_t)(row - H_DIM) * D_DIM + k);
    float4 a = ((const float4*)srcp)[0], b = ((const float4*)srcp)[1];
    float f[8] = {a.x, a.y, a.z, a.w, b.x, b.y, b.z, b.w};
    union { __nv_bfloat16 h[8]; uint4 u; } H, L;
#pragma unroll
    for (int j = 0; j < 8; j++) {
        __nv_bfloat16 hi = __float2bfloat16(f[j]);
        H.h[j] = hi;
        L.h[j] = __float2bfloat16(f[j] - __bfloat162float(hi));
    }
    __nv_bfloat16* dst = g_w2 + (size_t)row * K2 + k;
    *(uint4*)dst = H.u;
    *(uint4*)(dst + 1024) = L.u;
}

// ---------------- GEMM ------------------------------------------------------
// 3-term source map: chunk -> (A k-offset, B k-offset)
//   [0,16):  hi.hi   kA = c*64,          kB = c*64
//   [16,32): lo.hi   kA = 1024+(c-16)*64 kB = (c-16)*64
//   [32,48): hi.lo   kA = (c-32)*64      kB = 1024+(c-32)*64
__device__ __forceinline__ void chunk_ks(int c, int& kA, int& kB) {
    if (c < 16)      { kA = c * KC;               kB = c * KC; }
    else if (c < 32) { kA = 1024 + (c - 16) * KC; kB = (c - 16) * KC; }
    else             { kA = (c - 32) * KC;        kB = 1024 + (c - 32) * KC; }
}

__device__ __forceinline__ void load_chunk(uint32_t dstA, uint32_t dstB,
                                           int m0, int n0, int c, int tid) {
    int kA, kB;
    chunk_ks(c, kA, kB);
    const char* pA = (const char*)(g_x2 + (size_t)m0 * K2 + kA);
    const char* pB = (const char*)(g_w2 + (size_t)n0 * K2 + kB);
#pragma unroll
    for (int i = 0; i < 4; i++) {
        int gid = i * 256 + tid;       // 0..1023
        int r = gid >> 3;              // row 0..127
        int cb = gid & 7;              // 16B granule
        uint32_t bo = (uint32_t)(r * 128 + cb * 16);
        uint32_t sw = bo ^ ((bo >> 3) & 0x70);
        size_t goff = (size_t)r * (K2 * 2) + cb * 16;
        cp_async16(dstA + sw, pA + goff);
        cp_async16(dstB + sw, pB + goff);
    }
}

__global__ void __launch_bounds__(256, 2)
gemm_k(const float* __restrict__ bz, const float* __restrict__ bh) {
    extern __shared__ __align__(1024) char smem[];
    const uint32_t sb = s2u(smem);
    const int tid = threadIdx.x;
    const int wid = tid >> 5, lane = tid & 31;
    const int nt = blockIdx.x;   // 0..15
    const int mt = blockIdx.y;   // 0..255
    const int m0 = mt * 128, n0 = nt * 128;

    const int warp_m = wid & 1;  // 2
    const int warp_n = wid >> 1; // 4

    const int rowA = lane & 15, kqA = lane >> 4;
    const int rowB = (lane & 7) + ((lane >> 4) << 3);
    const int kqB = (lane >> 3) & 1;
    const uint32_t xorA = (uint32_t)((rowA & 7) << 4);
    const uint32_t xorB = (uint32_t)((rowB & 7) << 4);
    uint32_t rbyteA[4], rbyteB[2];
#pragma unroll
    for (int im = 0; im < 4; im++)
        rbyteA[im] = (uint32_t)((warp_m * 64 + im * 16 + rowA) * 128);
#pragma unroll
    for (int ib = 0; ib < 2; ib++)
        rbyteB[ib] = (uint32_t)((warp_n * 32 + ib * 16 + rowB) * 128);

    float acc[4][4][4];
#pragma unroll
    for (int im = 0; im < 4; im++)
#pragma unroll
        for (int in = 0; in < 4; in++)
#pragma unroll
            for (int q = 0; q < 4; q++) acc[im][in][q] = 0.0f;

    // prologue: stages 0,1
    load_chunk(sb, sb + TILE_B, m0, n0, 0, tid); cp_commit();
    load_chunk(sb + STG_B, sb + STG_B + TILE_B, m0, n0, 1, tid); cp_commit();

    for (int c = 0; c < NCHUNK; c++) {
        cp_wait1();
        __syncthreads();
        const int s = c % NSTG;
        const uint32_t baseA = sb + s * STG_B;
        const uint32_t baseB = baseA + TILE_B;
#pragma unroll
        for (int kk = 0; kk < 4; kk++) {
            uint32_t ra[4][4], rb[2][4];
#pragma unroll
            for (int im = 0; im < 4; im++)
                ldsm4(ra[im], baseA + rbyteA[im] + (((uint32_t)(kk * 32 + kqA * 16)) ^ xorA));
#pragma unroll
            for (int ib = 0; ib < 2; ib++)
                ldsm4(rb[ib], baseB + rbyteB[ib] + (((uint32_t)(kk * 32 + kqB * 16)) ^ xorB));
#pragma unroll
            for (int im = 0; im < 4; im++)
#pragma unroll
                for (int in = 0; in < 4; in++)
                    mma16816(acc[im][in], ra[im], rb[in >> 1][(in & 1) * 2], rb[in >> 1][(in & 1) * 2 + 1]);
        }
        __syncthreads();
        if (c + 2 < NCHUNK) {
            const int s2 = (c + 2) % NSTG;
            load_chunk(sb + s2 * STG_B, sb + s2 * STG_B + TILE_B, m0, n0, c + 2, tid);
        }
        cp_commit();
    }

    // epilogue: bias + (sigmoid) -> g_zb / g_hb
    const bool zt = (nt < 8);
    const float* bias = zt ? bz : bh;
    float* buf = zt ? g_zb : g_hb;
    const int nbase = n0 - (zt ? 0 : 1024);

#pragma unroll
    for (int in = 0; in < 4; in++) {
        const int col = nbase + warp_n * 32 + in * 8 + (lane & 3) * 2;
        const float b0 = __ldg(&bias[col]);
        const float b1 = __ldg(&bias[col + 1]);
#pragma unroll
        for (int im = 0; im < 4; im++) {
            const int row = m0 + warp_m * 64 + im * 16 + (lane >> 2);
            float v0 = acc[im][in][0] + b0;
            float v1 = acc[im][in][1] + b1;
            float v2 = acc[im][in][2] + b0;
            float v3 = acc[im][in][3] + b1;
            if (zt) {
                v0 = 1.0f / (1.0f + __expf(-v0));
                v1 = 1.0f / (1.0f + __expf(-v1));
                v2 = 1.0f / (1.0f + __expf(-v2));
                v3 = 1.0f / (1.0f + __expf(-v3));
            }
            *(float2*)(buf + (size_t)row * H_DIM + col) = make_float2(v0, v1);
            *(float2*)(buf + (size_t)(row + 8) * H_DIM + col) = make_float2(v2, v3);
        }
    }
}

// ---------------- scan kernel -----------------------------------------------
__global__ void scan_k(const float* __restrict__ h0, float* __restrict__ out) {
    const int idx = blockIdx.x * blockDim.x + threadIdx.x;  // 0..16383
    const int b = idx >> 10;
    const int h = idx & 1023;
    float hh = h0[idx];
    const size_t base = ((size_t)b * T_DIM) * H_DIM + h;
    const float* zp = g_zb + base;
    const float* hp = g_hb + base;
    float* op = out + base;
#pragma unroll 8
    for (int t = 0; t < T_DIM; t++) {
        const float z = zp[(size_t)t * H_DIM];
        const float ht = hp[(size_t)t * H_DIM];
        hh = fmaf(z, ht - hh, hh);      // (1-z)h + z*ht
        op[(size_t)t * H_DIM] = hh;
    }
}

// ---------------- launch -----------------------------------------------------
extern "C" void kernel_launch(void* const* d_in, const int* in_sizes, int n_in,
                              void* d_out, int out_size) {
    const float* x  = (const float*)d_in[0];
    const float* h0 = (const float*)d_in[1];
    const float* Wz = (const float*)d_in[2];
    const float* bz = (const float*)d_in[3];
    const float* Wh = (const float*)d_in[4];
    const float* bh = (const float*)d_in[5];
    float* out = (float*)d_out;

    cudaFuncSetAttribute(gemm_k, cudaFuncAttributeMaxDynamicSharedMemorySize, SMEM_TOTAL);

    split_x_k<<<16384, 256>>>(x);
    split_w_k<<<1024, 256>>>(Wz, Wh);
    // n fastest: CTAs sharing an X m-tile run concurrently (L2 reuse)
    gemm_k<<<dim3(16, 256, 1), 256, SMEM_TOTAL>>>(bz, bh);
    scan_k<<<128, 128>>>(h0, out);
}

// round 8
// speedup vs baseline: 1.0070x; 1.0070x over previous
#include <cuda_runtime.h>
#include <cuda_bf16.h>
#include <cstdint>
#include <cstddef>

// ---------------------------------------------------------------------------
// MinGRU: 3-term split-bf16 GEMM (x_hi.w_hi + x_lo.w_hi + x_hi.w_lo) via
// mma.sync.m16n8k16 + cp.async pipeline, with FUSED per-k0 stages:
// each stage loads x_hi/x_lo/w_hi/w_lo tiles ONCE (4 tiles instead of 6)
// cutting L2 tile traffic 6.4GB -> 4.3GB. Then bias/sigmoid epilogue and a
// T-SEGMENTED parallel affine scan (16 segments, summary + replay passes).
// ---------------------------------------------------------------------------

#define B_DIM 16
#define T_DIM 2048
#define D_DIM 1024
#define H_DIM 1024
#define M_TOT (B_DIM * T_DIM)   // 32768
#define N_TOT (2 * H_DIM)       // 2048
#define K2    (2 * D_DIM)       // 2048 (hi | lo halves)

#define KC      64              // K elems per stage (128B rows)
#define NSTG    3
#define NK0     16              // 1024 / 64 k0-stages
#define TILE_B  (128 * 128)     // 16KB per tile
#define STG_B   (4 * TILE_B)    // x_hi + x_lo + w_hi + w_lo = 64KB
#define SMEM_TOTAL (NSTG * STG_B)  // 196608

#define SEG     16              // scan segments
#define SEGLEN  (T_DIM / SEG)   // 128
#define NLANES  (B_DIM * H_DIM) // 16384

// ---------------- scratch (static device memory; no allocation) -------------
__device__ __align__(256) __nv_bfloat16 g_x2[(size_t)M_TOT * K2];   // [hi|lo]
__device__ __align__(256) __nv_bfloat16 g_w2[(size_t)N_TOT * K2];   // [hi|lo]
__device__ __align__(256) float g_zb[(size_t)M_TOT * H_DIM];        // gates
__device__ __align__(256) float g_hb[(size_t)M_TOT * H_DIM];        // candidates
__device__ __align__(256) float g_P[SEG][NLANES];                   // seg prod
__device__ __align__(256) float g_Q[SEG][NLANES];                   // seg offset

// ---------------- PTX helpers ----------------------------------------------
__device__ __forceinline__ uint32_t s2u(const void* p) {
    return (uint32_t)__cvta_generic_to_shared(p);
}
__device__ __forceinline__ void cp_async16(uint32_t dst, const void* src) {
    asm volatile("cp.async.cg.shared.global [%0], [%1], 16;" :: "r"(dst), "l"(src) : "memory");
}
__device__ __forceinline__ void cp_commit() {
    asm volatile("cp.async.commit_group;" ::: "memory");
}
__device__ __forceinline__ void cp_wait1() {
    asm volatile("cp.async.wait_group 1;" ::: "memory");
}
__device__ __forceinline__ void ldsm4(uint32_t* r, uint32_t addr) {
    asm volatile("ldmatrix.sync.aligned.m8n8.x4.shared.b16 {%0,%1,%2,%3}, [%4];"
                 : "=r"(r[0]), "=r"(r[1]), "=r"(r[2]), "=r"(r[3]) : "r"(addr));
}
__device__ __forceinline__ void mma16816(float* d, const uint32_t* a, uint32_t b0, uint32_t b1) {
    asm volatile("mma.sync.aligned.m16n8k16.row.col.f32.bf16.bf16.f32 "
                 "{%0,%1,%2,%3}, {%4,%5,%6,%7}, {%8,%9}, {%0,%1,%2,%3};"
                 : "+f"(d[0]), "+f"(d[1]), "+f"(d[2]), "+f"(d[3])
                 : "r"(a[0]), "r"(a[1]), "r"(a[2]), "r"(a[3]), "r"(b0), "r"(b1));
}

// ---------------- split kernels ---------------------------------------------
__global__ void split_x_k(const float* __restrict__ x) {
    size_t i = (size_t)blockIdx.x * blockDim.x + threadIdx.x;  // group of 8 elems
    size_t e = i * 8;
    size_t row = e >> 10;
    int k = (int)(e & 1023);
    const float4* src = (const float4*)(x + e);
    float4 a = src[0], b = src[1];
    float f[8] = {a.x, a.y, a.z, a.w, b.x, b.y, b.z, b.w};
    union { __nv_bfloat16 h[8]; uint4 u; } H, L;
#pragma unroll
    for (int j = 0; j < 8; j++) {
        __nv_bfloat16 hi = __float2bfloat16(f[j]);
        H.h[j] = hi;
        L.h[j] = __float2bfloat16(f[j] - __bfloat162float(hi));
    }
    __nv_bfloat16* dst = g_x2 + row * K2 + k;
    *(uint4*)dst = H.u;
    *(uint4*)(dst + 1024) = L.u;
}

__global__ void split_w_k(const float* __restrict__ Wz, const float* __restrict__ Wh) {
    size_t i = (size_t)blockIdx.x * blockDim.x + threadIdx.x;
    size_t e = i * 8;
    int row = (int)(e >> 10);
    int k = (int)(e & 1023);
    const float* srcp = (row < H_DIM) ? (Wz + (size_t)row * D_DIM + k)
                                      : (Wh + (size_t)(row - H_DIM) * D_DIM + k);
    float4 a = ((const float4*)srcp)[0], b = ((const float4*)srcp)[1];
    float f[8] = {a.x, a.y, a.z, a.w, b.x, b.y, b.z, b.w};
    union { __nv_bfloat16 h[8]; uint4 u; } H, L;
#pragma unroll
    for (int j = 0; j < 8; j++) {
        __nv_bfloat16 hi = __float2bfloat16(f[j]);
        H.h[j] = hi;
        L.h[j] = __float2bfloat16(f[j] - __bfloat162float(hi));
    }
    __nv_bfloat16* dst = g_w2 + (size_t)row * K2 + k;
    *(uint4*)dst = H.u;
    *(uint4*)(dst + 1024) = L.u;
}

// ---------------- GEMM ------------------------------------------------------
// One stage = 4 tiles at dst+{0,16K,32K,48K}: x_hi, x_lo, w_hi, w_lo for k0.
__device__ __forceinline__ void load_stage(uint32_t dst, int m0, int n0, int k0, int tid) {
    const char* pXh = (const char*)(g_x2 + (size_t)m0 * K2 + k0);
    const char* pWh = (const char*)(g_w2 + (size_t)n0 * K2 + k0);
#pragma unroll
    for (int i = 0; i < 4; i++) {
        int gid = i * 256 + tid;       // 0..1023
        int r = gid >> 3;              // row 0..127
        int cb = gid & 7;              // 16B granule
        uint32_t bo = (uint32_t)(r * 128 + cb * 16);
        uint32_t sw = bo ^ ((bo >> 3) & 0x70);
        size_t goff = (size_t)r * (K2 * 2) + cb * 16;
        cp_async16(dst + sw,              pXh + goff);          // x_hi
        cp_async16(dst + TILE_B + sw,     pXh + 2048 + goff);   // x_lo (+1024 elems)
        cp_async16(dst + 2 * TILE_B + sw, pWh + goff);          // w_hi
        cp_async16(dst + 3 * TILE_B + sw, pWh + 2048 + goff);   // w_lo
    }
}

__global__ void __launch_bounds__(256, 1)
gemm_k(const float* __restrict__ bz, const float* __restrict__ bh) {
    extern __shared__ __align__(1024) char smem[];
    const uint32_t sb = s2u(smem);
    const int tid = threadIdx.x;
    const int wid = tid >> 5, lane = tid & 31;
    const int nt = blockIdx.x;   // 0..15
    const int mt = blockIdx.y;   // 0..255
    const int m0 = mt * 128, n0 = nt * 128;

    const int warp_m = wid & 1;  // 2
    const int warp_n = wid >> 1; // 4

    const int rowA = lane & 15, kqA = lane >> 4;
    const int rowB = (lane & 7) + ((lane >> 4) << 3);
    const int kqB = (lane >> 3) & 1;
    const uint32_t xorA = (uint32_t)((rowA & 7) << 4);
    const uint32_t xorB = (uint32_t)((rowB & 7) << 4);
    uint32_t rbyteA[4], rbyteB[2];
#pragma unroll
    for (int im = 0; im < 4; im++)
        rbyteA[im] = (uint32_t)((warp_m * 64 + im * 16 + rowA) * 128);
#pragma unroll
    for (int ib = 0; ib < 2; ib++)
        rbyteB[ib] = (uint32_t)((warp_n * 32 + ib * 16 + rowB) * 128);

    float acc[4][4][4];
#pragma unroll
    for (int im = 0; im < 4; im++)
#pragma unroll
        for (int in = 0; in < 4; in++)
#pragma unroll
            for (int q = 0; q < 4; q++) acc[im][in][q] = 0.0f;

    // prologue: stages 0,1
    load_stage(sb, m0, n0, 0, tid); cp_commit();
    load_stage(sb + STG_B, m0, n0, KC, tid); cp_commit();

    for (int c = 0; c < NK0; c++) {
        cp_wait1();
        __syncthreads();
        const uint32_t base = sb + (c % NSTG) * STG_B;
        const uint32_t baseXh = base;
        const uint32_t baseXl = base + TILE_B;
        const uint32_t baseWh = base + 2 * TILE_B;
        const uint32_t baseWl = base + 3 * TILE_B;
#pragma unroll
        for (int kk = 0; kk < 4; kk++) {
            const uint32_t offA = ((uint32_t)(kk * 32 + kqA * 16)) ^ xorA;
            const uint32_t offB = ((uint32_t)(kk * 32 + kqB * 16)) ^ xorB;
            uint32_t raH[4][4], raL[4][4], rbH[2][4], rbL[2][4];
            // hi.hi
#pragma unroll
            for (int im = 0; im < 4; im++) ldsm4(raH[im], baseXh + rbyteA[im] + offA);
#pragma unroll
            for (int ib = 0; ib < 2; ib++) ldsm4(rbH[ib], baseWh + rbyteB[ib] + offB);
#pragma unroll
            for (int im = 0; im < 4; im++)
#pragma unroll
                for (int in = 0; in < 4; in++)
                    mma16816(acc[im][in], raH[im], rbH[in >> 1][(in & 1) * 2], rbH[in >> 1][(in & 1) * 2 + 1]);
            // lo.hi (reuse rbH)
#pragma unroll
            for (int im = 0; im < 4; im++) ldsm4(raL[im], baseXl + rbyteA[im] + offA);
#pragma unroll
            for (int im = 0; im < 4; im++)
#pragma unroll
                for (int in = 0; in < 4; in++)
                    mma16816(acc[im][in], raL[im], rbH[in >> 1][(in & 1) * 2], rbH[in >> 1][(in & 1) * 2 + 1]);
            // hi.lo (reuse raH)
#pragma unroll
            for (int ib = 0; ib < 2; ib++) ldsm4(rbL[ib], baseWl + rbyteB[ib] + offB);
#pragma unroll
            for (int im = 0; im < 4; im++)
#pragma unroll
                for (int in = 0; in < 4; in++)
                    mma16816(acc[im][in], raH[im], rbL[in >> 1][(in & 1) * 2], rbL[in >> 1][(in & 1) * 2 + 1]);
        }
        __syncthreads();
        if (c + 2 < NK0) {
            load_stage(sb + ((c + 2) % NSTG) * STG_B, m0, n0, (c + 2) * KC, tid);
        }
        cp_commit();
    }

    // epilogue: bias + (sigmoid) -> g_zb / g_hb
    const bool zt = (nt < 8);
    const float* bias = zt ? bz : bh;
    float* buf = zt ? g_zb : g_hb;
    const int nbase = n0 - (zt ? 0 : 1024);

#pragma unroll
    for (int in = 0; in < 4; in++) {
        const int col = nbase + warp_n * 32 + in * 8 + (lane & 3) * 2;
        const float b0 = __ldg(&bias[col]);
        const float b1 = __ldg(&bias[col + 1]);
#pragma unroll
        for (int im = 0; im < 4; im++) {
            const int row = m0 + warp_m * 64 + im * 16 + (lane >> 2);
            float v0 = acc[im][in][0] + b0;
            float v1 = acc[im][in][1] + b1;
            float v2 = acc[im][in][2] + b0;
            float v3 = acc[im][in][3] + b1;
            if (zt) {
                v0 = 1.0f / (1.0f + __expf(-v0));
                v1 = 1.0f / (1.0f + __expf(-v1));
                v2 = 1.0f / (1.0f + __expf(-v2));
                v3 = 1.0f / (1.0f + __expf(-v3));
            }
            *(float2*)(buf + (size_t)row * H_DIM + col) = make_float2(v0, v1);
            *(float2*)(buf + (size_t)(row + 8) * H_DIM + col) = make_float2(v2, v3);
        }
    }
}

// ---------------- scan: segment summaries then replay ------------------------
// h_t = a h_{t-1} + b with a = 1-z, b = z*h~. Segment composition:
// (P,Q): h_end = Q + P * h_start.   Pass 1 over segs 0..SEG-2.
__global__ void scan_sum_k() {
    const int idx = blockIdx.x * blockDim.x + threadIdx.x;  // (SEG-1)*16384 lanes
    const int seg = idx >> 14;          // 0..14
    const int lane = idx & (NLANES - 1);
    const int b = lane >> 10;
    const int h = lane & 1023;
    const size_t base = ((size_t)b * T_DIM + seg * SEGLEN) * H_DIM + h;
    const float* zp = g_zb + base;
    const float* hp = g_hb + base;
    float P = 1.0f, Q = 0.0f;
#pragma unroll 8
    for (int t = 0; t < SEGLEN; t++) {
        const float z = zp[(size_t)t * H_DIM];
        const float ht = hp[(size_t)t * H_DIM];
        const float a = 1.0f - z;
        P *= a;
        Q = fmaf(a, Q, z * ht);
    }
    g_P[seg][lane] = P;
    g_Q[seg][lane] = Q;
}

__global__ void scan_final_k(const float* __restrict__ h0, float* __restrict__ out) {
    const int idx = blockIdx.x * blockDim.x + threadIdx.x;  // SEG*16384 lanes
    const int seg = idx >> 14;          // 0..15
    const int lane = idx & (NLANES - 1);
    const int b = lane >> 10;
    const int h = lane & 1023;
    float hh = h0[lane];
    for (int s = 0; s < seg; s++)
        hh = fmaf(g_P[s][lane], hh, g_Q[s][lane]);
    const size_t base = ((size_t)b * T_DIM + seg * SEGLEN) * H_DIM + h;
    const float* zp = g_zb + base;
    const float* hp = g_hb + base;
    float* op = out + base;
#pragma unroll 8
    for (int t = 0; t < SEGLEN; t++) {
        const float z = zp[(size_t)t * H_DIM];
        const float ht = hp[(size_t)t * H_DIM];
        hh = fmaf(z, ht - hh, hh);
        op[(size_t)t * H_DIM] = hh;
    }
}

// ---------------- launch -----------------------------------------------------
extern "C" void kernel_launch(void* const* d_in, const int* in_sizes, int n_in,
                              void* d_out, int out_size) {
    const float* x  = (const float*)d_in[0];
    const float* h0 = (const float*)d_in[1];
    const float* Wz = (const float*)d_in[2];
    const float* bz = (const float*)d_in[3];
    const float* Wh = (const float*)d_in[4];
    const float* bh = (const float*)d_in[5];
    float* out = (float*)d_out;

    cudaFuncSetAttribute(gemm_k, cudaFuncAttributeMaxDynamicSharedMemorySize, SMEM_TOTAL);

    split_x_k<<<16384, 256>>>(x);
    split_w_k<<<1024, 256>>>(Wz, Wh);
    // n fastest: CTAs sharing an X m-tile run concurrently (L2 reuse)
    gemm_k<<<dim3(16, 256, 1), 256, SMEM_TOTAL>>>(bz, bh);
    // scan: (SEG-1)*16384/256 = 960 blocks, then SEG*16384/256 = 1024
    scan_sum_k<<<960, 256>>>();
    scan_final_k<<<1024, 256>>>(h0, out);
}

// round 9
// speedup vs baseline: 2.3741x; 2.3576x over previous
#include <cuda_runtime.h>
#include <cuda_fp16.h>
#include <cstdint>
#include <cstddef>

// ---------------------------------------------------------------------------
// MinGRU: SINGLE-PASS fp16 GEMM via mma.sync.m16n8k16.f32.f16.f16.f32.
// R8 evidence: GEMM is mma.sync-throughput bound (~392 TF/s ceiling), NOT
// L2-bound (cutting traffic 33% changed nothing). So cut MMA work 3x:
// fp16 (half-ulp 2^-12) single product gives predicted rel_err ~3.6e-4
// (validated error model: bf16 level measured 2.894e-3 = 8x higher).
// Then bias/sigmoid epilogue and the proven segmented affine scan.
// ---------------------------------------------------------------------------

#define B_DIM 16
#define T_DIM 2048
#define D_DIM 1024
#define H_DIM 1024
#define M_TOT (B_DIM * T_DIM)   // 32768
#define N_TOT (2 * H_DIM)       // 2048
#define K_TOT D_DIM             // 1024

#define KC      64              // K elems per stage (128B fp16 rows)
#define NSTG    3
#define NCHUNK  (K_TOT / KC)    // 16
#define TILE_B  (128 * 128)     // 16KB: 128 rows x 128 bytes
#define STG_B   (2 * TILE_B)    // A + B = 32KB
#define SMEM_TOTAL (NSTG * STG_B)  // 98304 -> 2 CTAs/SM

#define SEG     16              // scan segments
#define SEGLEN  (T_DIM / SEG)   // 128
#define NLANES  (B_DIM * H_DIM) // 16384

// ---------------- scratch (static device memory; no allocation) -------------
__device__ __align__(256) __half g_xh[(size_t)M_TOT * K_TOT];   // 64MB
__device__ __align__(256) __half g_wh[(size_t)N_TOT * K_TOT];   // 4MB
__device__ __align__(256) float g_zb[(size_t)M_TOT * H_DIM];    // gates
__device__ __align__(256) float g_hb[(size_t)M_TOT * H_DIM];    // candidates
__device__ __align__(256) float g_P[SEG][NLANES];               // seg prod
__device__ __align__(256) float g_Q[SEG][NLANES];               // seg offset

// ---------------- PTX helpers ----------------------------------------------
__device__ __forceinline__ uint32_t s2u(const void* p) {
    return (uint32_t)__cvta_generic_to_shared(p);
}
__device__ __forceinline__ void cp_async16(uint32_t dst, const void* src) {
    asm volatile("cp.async.cg.shared.global [%0], [%1], 16;" :: "r"(dst), "l"(src) : "memory");
}
__device__ __forceinline__ void cp_commit() {
    asm volatile("cp.async.commit_group;" ::: "memory");
}
__device__ __forceinline__ void cp_wait1() {
    asm volatile("cp.async.wait_group 1;" ::: "memory");
}
__device__ __forceinline__ void ldsm4(uint32_t* r, uint32_t addr) {
    asm volatile("ldmatrix.sync.aligned.m8n8.x4.shared.b16 {%0,%1,%2,%3}, [%4];"
                 : "=r"(r[0]), "=r"(r[1]), "=r"(r[2]), "=r"(r[3]) : "r"(addr));
}
__device__ __forceinline__ void mma16816(float* d, const uint32_t* a, uint32_t b0, uint32_t b1) {
    asm volatile("mma.sync.aligned.m16n8k16.row.col.f32.f16.f16.f32 "
                 "{%0,%1,%2,%3}, {%4,%5,%6,%7}, {%8,%9}, {%0,%1,%2,%3};"
                 : "+f"(d[0]), "+f"(d[1]), "+f"(d[2]), "+f"(d[3])
                 : "r"(a[0]), "r"(a[1]), "r"(a[2]), "r"(a[3]), "r"(b0), "r"(b1));
}

// ---------------- convert kernels -------------------------------------------
__global__ void conv_x_k(const float* __restrict__ x) {
    size_t i = (size_t)blockIdx.x * blockDim.x + threadIdx.x;  // group of 8 elems
    size_t e = i * 8;
    const float4* src = (const float4*)(x + e);
    float4 a = src[0], b = src[1];
    float f[8] = {a.x, a.y, a.z, a.w, b.x, b.y, b.z, b.w};
    union { __half h[8]; uint4 u; } H;
#pragma unroll
    for (int j = 0; j < 8; j++) H.h[j] = __float2half_rn(f[j]);
    ((uint4*)g_xh)[i] = H.u;
}

// W rows: n<1024 -> Wz[n], else Wh[n-1024]
__global__ void conv_w_k(const float* __restrict__ Wz, const float* __restrict__ Wh) {
    size_t i = (size_t)blockIdx.x * blockDim.x + threadIdx.x;
    size_t e = i * 8;
    int row = (int)(e >> 10);
    int k = (int)(e & 1023);
    const float* srcp = (row < H_DIM) ? (Wz + (size_t)row * D_DIM + k)
                                      : (Wh + (size_t)(row - H_DIM) * D_DIM + k);
    float4 a = ((const float4*)srcp)[0], b = ((const float4*)srcp)[1];
    float f[8] = {a.x, a.y, a.z, a.w, b.x, b.y, b.z, b.w};
    union { __half h[8]; uint4 u; } H;
#pragma unroll
    for (int j = 0; j < 8; j++) H.h[j] = __float2half_rn(f[j]);
    ((uint4*)g_wh)[i] = H.u;
}

// ---------------- GEMM ------------------------------------------------------
// Stage: A tile (128 x 64 fp16) + B tile, SW-swizzled 128B rows.
__device__ __forceinline__ void load_stage(uint32_t dst, int m0, int n0, int k0, int tid) {
    const char* pA = (const char*)(g_xh + (size_t)m0 * K_TOT + k0);
    const char* pB = (const char*)(g_wh + (size_t)n0 * K_TOT + k0);
#pragma unroll
    for (int i = 0; i < 4; i++) {
        int gid = i * 256 + tid;       // 0..1023
        int r = gid >> 3;              // row 0..127
        int cb = gid & 7;              // 16B granule
        uint32_t bo = (uint32_t)(r * 128 + cb * 16);
        uint32_t sw = bo ^ ((bo >> 3) & 0x70);
        size_t goff = (size_t)r * (K_TOT * 2) + cb * 16;
        cp_async16(dst + sw,          pA + goff);
        cp_async16(dst + TILE_B + sw, pB + goff);
    }
}

__global__ void __launch_bounds__(256, 2)
gemm_k(const float* __restrict__ bz, const float* __restrict__ bh) {
    extern __shared__ __align__(1024) char smem[];
    const uint32_t sb = s2u(smem);
    const int tid = threadIdx.x;
    const int wid = tid >> 5, lane = tid & 31;
    const int nt = blockIdx.x;   // 0..15
    const int mt = blockIdx.y;   // 0..255
    const int m0 = mt * 128, n0 = nt * 128;

    const int warp_m = wid & 1;  // 2
    const int warp_n = wid >> 1; // 4

    const int rowA = lane & 15, kqA = lane >> 4;
    const int rowB = (lane & 7) + ((lane >> 4) << 3);
    const int kqB = (lane >> 3) & 1;
    const uint32_t xorA = (uint32_t)((rowA & 7) << 4);
    const uint32_t xorB = (uint32_t)((rowB & 7) << 4);
    uint32_t rbyteA[4], rbyteB[2];
#pragma unroll
    for (int im = 0; im < 4; im++)
        rbyteA[im] = (uint32_t)((warp_m * 64 + im * 16 + rowA) * 128);
#pragma unroll
    for (int ib = 0; ib < 2; ib++)
        rbyteB[ib] = (uint32_t)((warp_n * 32 + ib * 16 + rowB) * 128);

    float acc[4][4][4];
#pragma unroll
    for (int im = 0; im < 4; im++)
#pragma unroll
        for (int in = 0; in < 4; in++)
#pragma unroll
            for (int q = 0; q < 4; q++) acc[im][in][q] = 0.0f;

    // prologue: stages 0,1
    load_stage(sb, m0, n0, 0, tid); cp_commit();
    load_stage(sb + STG_B, m0, n0, KC, tid); cp_commit();

    for (int c = 0; c < NCHUNK; c++) {
        cp_wait1();
        __syncthreads();
        const uint32_t baseA = sb + (c % NSTG) * STG_B;
        const uint32_t baseB = baseA + TILE_B;
#pragma unroll
        for (int kk = 0; kk < 4; kk++) {
            const uint32_t offA = ((uint32_t)(kk * 32 + kqA * 16)) ^ xorA;
            const uint32_t offB = ((uint32_t)(kk * 32 + kqB * 16)) ^ xorB;
            uint32_t ra[4][4], rb[2][4];
#pragma unroll
            for (int im = 0; im < 4; im++) ldsm4(ra[im], baseA + rbyteA[im] + offA);
#pragma unroll
            for (int ib = 0; ib < 2; ib++) ldsm4(rb[ib], baseB + rbyteB[ib] + offB);
#pragma unroll
            for (int im = 0; im < 4; im++)
#pragma unroll
                for (int in = 0; in < 4; in++)
                    mma16816(acc[im][in], ra[im], rb[in >> 1][(in & 1) * 2], rb[in >> 1][(in & 1) * 2 + 1]);
        }
        __syncthreads();
        if (c + 2 < NCHUNK) {
            load_stage(sb + ((c + 2) % NSTG) * STG_B, m0, n0, (c + 2) * KC, tid);
        }
        cp_commit();
    }

    // epilogue: bias + (sigmoid) -> g_zb / g_hb
    const bool zt = (nt < 8);
    const float* bias = zt ? bz : bh;
    float* buf = zt ? g_zb : g_hb;
    const int nbase = n0 - (zt ? 0 : 1024);

#pragma unroll
    for (int in = 0; in < 4; in++) {
        const int col = nbase + warp_n * 32 + in * 8 + (lane & 3) * 2;
        const float b0 = __ldg(&bias[col]);
        const float b1 = __ldg(&bias[col + 1]);
#pragma unroll
        for (int im = 0; im < 4; im++) {
            const int row = m0 + warp_m * 64 + im * 16 + (lane >> 2);
            float v0 = acc[im][in][0] + b0;
            float v1 = acc[im][in][1] + b1;
            float v2 = acc[im][in][2] + b0;
            float v3 = acc[im][in][3] + b1;
            if (zt) {
                v0 = 1.0f / (1.0f + __expf(-v0));
                v1 = 1.0f / (1.0f + __expf(-v1));
                v2 = 1.0f / (1.0f + __expf(-v2));
                v3 = 1.0f / (1.0f + __expf(-v3));
            }
            *(float2*)(buf + (size_t)row * H_DIM + col) = make_float2(v0, v1);
            *(float2*)(buf + (size_t)(row + 8) * H_DIM + col) = make_float2(v2, v3);
        }
    }
}

// ---------------- scan: segment summaries then replay ------------------------
__global__ void scan_sum_k() {
    const int idx = blockIdx.x * blockDim.x + threadIdx.x;  // (SEG-1)*16384 lanes
    const int seg = idx >> 14;          // 0..14
    const int lane = idx & (NLANES - 1);
    const int b = lane >> 10;
    const int h = lane & 1023;
    const size_t base = ((size_t)b * T_DIM + seg * SEGLEN) * H_DIM + h;
    const float* zp = g_zb + base;
    const float* hp = g_hb + base;
    float P = 1.0f, Q = 0.0f;
#pragma unroll 8
    for (int t = 0; t < SEGLEN; t++) {
        const float z = zp[(size_t)t * H_DIM];
        const float ht = hp[(size_t)t * H_DIM];
        const float a = 1.0f - z;
        P *= a;
        Q = fmaf(a, Q, z * ht);
    }
    g_P[seg][lane] = P;
    g_Q[seg][lane] = Q;
}

__global__ void scan_final_k(const float* __restrict__ h0, float* __restrict__ out) {
    const int idx = blockIdx.x * blockDim.x + threadIdx.x;  // SEG*16384 lanes
    const int seg = idx >> 14;          // 0..15
    const int lane = idx & (NLANES - 1);
    const int b = lane >> 10;
    const int h = lane & 1023;
    float hh = h0[lane];
    for (int s = 0; s < seg; s++)
        hh = fmaf(g_P[s][lane], hh, g_Q[s][lane]);
    const size_t base = ((size_t)b * T_DIM + seg * SEGLEN) * H_DIM + h;
    const float* zp = g_zb + base;
    const float* hp = g_hb + base;
    float* op = out + base;
#pragma unroll 8
    for (int t = 0; t < SEGLEN; t++) {
        const float z = zp[(size_t)t * H_DIM];
        const float ht = hp[(size_t)t * H_DIM];
        hh = fmaf(z, ht - hh, hh);
        op[(size_t)t * H_DIM] = hh;
    }
}

// ---------------- launch -----------------------------------------------------
extern "C" void kernel_launch(void* const* d_in, const int* in_sizes, int n_in,
                              void* d_out, int out_size) {
    const float* x  = (const float*)d_in[0];
    const float* h0 = (const float*)d_in[1];
    const float* Wz = (const float*)d_in[2];
    const float* bz = (const float*)d_in[3];
    const float* Wh = (const float*)d_in[4];
    const float* bh = (const float*)d_in[5];
    float* out = (float*)d_out;

    cudaFuncSetAttribute(gemm_k, cudaFuncAttributeMaxDynamicSharedMemorySize, SMEM_TOTAL);

    conv_x_k<<<16384, 256>>>(x);
    conv_w_k<<<1024, 256>>>(Wz, Wh);
    // n fastest: CTAs sharing an X m-tile run concurrently; A+B fit in L2
    gemm_k<<<dim3(16, 256, 1), 256, SMEM_TOTAL>>>(bz, bh);
    scan_sum_k<<<960, 256>>>();
    scan_final_k<<<1024, 256>>>(h0, out);
}

// round 11
// speedup vs baseline: 2.5935x; 1.0924x over previous
#include <cuda_runtime.h>
#include <cuda_fp16.h>
#include <cstdint>
#include <cstddef>

// ---------------------------------------------------------------------------
// MinGRU: single-pass fp16 GEMM (mma.sync.m16n8k16) -- measured at the
// ~390 TF/s mma.sync ceiling -- plus fp16 STORAGE for the z / h~ intermediates
// (halves the DRAM traffic of epilogue + both scan passes; error model says
// +1-2.5e-4, total ~4.5e-4 < 1e-3). Segmented affine scan, 2 lanes/thread.
// ---------------------------------------------------------------------------

#define B_DIM 16
#define T_DIM 2048
#define D_DIM 1024
#define H_DIM 1024
#define M_TOT (B_DIM * T_DIM)   // 32768
#define N_TOT (2 * H_DIM)       // 2048
#define K_TOT D_DIM             // 1024

#define KC      64              // K elems per stage (128B fp16 rows)
#define NSTG    3
#define NCHUNK  (K_TOT / KC)    // 16
#define TILE_B  (128 * 128)     // 16KB
#define STG_B   (2 * TILE_B)    // A + B = 32KB
#define SMEM_TOTAL (NSTG * STG_B)  // 98304 -> 2 CTAs/SM

#define SEG     16              // scan segments
#define SEGLEN  (T_DIM / SEG)   // 128
#define NLANES  (B_DIM * H_DIM) // 16384

// ---------------- scratch (static device memory; no allocation) -------------
__device__ __align__(256) __half g_xh[(size_t)M_TOT * K_TOT];   // 64MB
__device__ __align__(256) __half g_wh[(size_t)N_TOT * K_TOT];   // 4MB
__device__ __align__(256) __half g_zb[(size_t)M_TOT * H_DIM];   // gates (fp16)
__device__ __align__(256) __half g_hb[(size_t)M_TOT * H_DIM];   // cands (fp16)
__device__ __align__(256) float g_P[SEG][NLANES];               // seg prod
__device__ __align__(256) float g_Q[SEG][NLANES];               // seg offset

// ---------------- PTX helpers ----------------------------------------------
__device__ __forceinline__ uint32_t s2u(const void* p) {
    return (uint32_t)__cvta_generic_to_shared(p);
}
__device__ __forceinline__ void cp_async16(uint32_t dst, const void* src) {
    asm volatile("cp.async.cg.shared.global [%0], [%1], 16;" :: "r"(dst), "l"(src) : "memory");
}
__device__ __forceinline__ void cp_commit() {
    asm volatile("cp.async.commit_group;" ::: "memory");
}
__device__ __forceinline__ void cp_wait1() {
    asm volatile("cp.async.wait_group 1;" ::: "memory");
}
__device__ __forceinline__ void ldsm4(uint32_t* r, uint32_t addr) {
    asm volatile("ldmatrix.sync.aligned.m8n8.x4.shared.b16 {%0,%1,%2,%3}, [%4];"
                 : "=r"(r[0]), "=r"(r[1]), "=r"(r[2]), "=r"(r[3]) : "r"(addr));
}
__device__ __forceinline__ void mma16816(float* d, const uint32_t* a, uint32_t b0, uint32_t b1) {
    asm volatile("mma.sync.aligned.m16n8k16.row.col.f32.f16.f16.f32 "
                 "{%0,%1,%2,%3}, {%4,%5,%6,%7}, {%8,%9}, {%0,%1,%2,%3};"
                 : "+f"(d[0]), "+f"(d[1]), "+f"(d[2]), "+f"(d[3])
                 : "r"(a[0]), "r"(a[1]), "r"(a[2]), "r"(a[3]), "r"(b0), "r"(b1));
}

// ---------------- convert kernels -------------------------------------------
__global__ void conv_x_k(const float* __restrict__ x) {
    size_t i = (size_t)blockIdx.x * blockDim.x + threadIdx.x;  // group of 8 elems
    size_t e = i * 8;
    const float4* src = (const float4*)(x + e);
    float4 a = src[0], b = src[1];
    float f[8] = {a.x, a.y, a.z, a.w, b.x, b.y, b.z, b.w};
    union { __half h[8]; uint4 u; } H;
#pragma unroll
    for (int j = 0; j < 8; j++) H.h[j] = __float2half_rn(f[j]);
    ((uint4*)g_xh)[i] = H.u;
}

__global__ void conv_w_k(const float* __restrict__ Wz, const float* __restrict__ Wh) {
    size_t i = (size_t)blockIdx.x * blockDim.x + threadIdx.x;
    size_t e = i * 8;
    int row = (int)(e >> 10);
    int k = (int)(e & 1023);
    const float* srcp = (row < H_DIM) ? (Wz + (size_t)row * D_DIM + k)
                                      : (Wh + (size_t)(row - H_DIM) * D_DIM + k);
    float4 a = ((const float4*)srcp)[0], b = ((const float4*)srcp)[1];
    float f[8] = {a.x, a.y, a.z, a.w, b.x, b.y, b.z, b.w};
    union { __half h[8]; uint4 u; } H;
#pragma unroll
    for (int j = 0; j < 8; j++) H.h[j] = __float2half_rn(f[j]);
    ((uint4*)g_wh)[i] = H.u;
}

// ---------------- GEMM ------------------------------------------------------
__device__ __forceinline__ void load_stage(uint32_t dst, int m0, int n0, int k0, int tid) {
    const char* pA = (const char*)(g_xh + (size_t)m0 * K_TOT + k0);
    const char* pB = (const char*)(g_wh + (size_t)n0 * K_TOT + k0);
#pragma unroll
    for (int i = 0; i < 4; i++) {
        int gid = i * 256 + tid;       // 0..1023
        int r = gid >> 3;              // row 0..127
        int cb = gid & 7;              // 16B granule
        uint32_t bo = (uint32_t)(r * 128 + cb * 16);
        uint32_t sw = bo ^ ((bo >> 3) & 0x70);
        size_t goff = (size_t)r * (K_TOT * 2) + cb * 16;
        cp_async16(dst + sw,          pA + goff);
        cp_async16(dst + TILE_B + sw, pB + goff);
    }
}

__global__ void __launch_bounds__(256, 2)
gemm_k(const float* __restrict__ bz, const float* __restrict__ bh) {
    extern __shared__ __align__(1024) char smem[];
    const uint32_t sb = s2u(smem);
    const int tid = threadIdx.x;
    const int wid = tid >> 5, lane = tid & 31;
    const int nt = blockIdx.x;   // 0..15
    const int mt = blockIdx.y;   // 0..255
    const int m0 = mt * 128, n0 = nt * 128;

    const int warp_m = wid & 1;  // 2
    const int warp_n = wid >> 1; // 4

    const int rowA = lane & 15, kqA = lane >> 4;
    const int rowB = (lane & 7) + ((lane >> 4) << 3);
    const int kqB = (lane >> 3) & 1;
    const uint32_t xorA = (uint32_t)((rowA & 7) << 4);
    const uint32_t xorB = (uint32_t)((rowB & 7) << 4);
    uint32_t rbyteA[4], rbyteB[2];
#pragma unroll
    for (int im = 0; im < 4; im++)
        rbyteA[im] = (uint32_t)((warp_m * 64 + im * 16 + rowA) * 128);
#pragma unroll
    for (int ib = 0; ib < 2; ib++)
        rbyteB[ib] = (uint32_t)((warp_n * 32 + ib * 16 + rowB) * 128);

    float acc[4][4][4];
#pragma unroll
    for (int im = 0; im < 4; im++)
#pragma unroll
        for (int in = 0; in < 4; in++)
#pragma unroll
            for (int q = 0; q < 4; q++) acc[im][in][q] = 0.0f;

    // prologue: stages 0,1
    load_stage(sb, m0, n0, 0, tid); cp_commit();
    load_stage(sb + STG_B, m0, n0, KC, tid); cp_commit();

    for (int c = 0; c < NCHUNK; c++) {
        cp_wait1();
        __syncthreads();
        const uint32_t baseA = sb + (c % NSTG) * STG_B;
        const uint32_t baseB = baseA + TILE_B;
#pragma unroll
        for (int kk = 0; kk < 4; kk++) {
            const uint32_t offA = ((uint32_t)(kk * 32 + kqA * 16)) ^ xorA;
            const uint32_t offB = ((uint32_t)(kk * 32 + kqB * 16)) ^ xorB;
            uint32_t ra[4][4], rb[2][4];
#pragma unroll
            for (int im = 0; im < 4; im++) ldsm4(ra[im], baseA + rbyteA[im] + offA);
#pragma unroll
            for (int ib = 0; ib < 2; ib++) ldsm4(rb[ib], baseB + rbyteB[ib] + offB);
#pragma unroll
            for (int im = 0; im < 4; im++)
#pragma unroll
                for (int in = 0; in < 4; in++)
                    mma16816(acc[im][in], ra[im], rb[in >> 1][(in & 1) * 2], rb[in >> 1][(in & 1) * 2 + 1]);
        }
        __syncthreads();
        if (c + 2 < NCHUNK) {
            load_stage(sb + ((c + 2) % NSTG) * STG_B, m0, n0, (c + 2) * KC, tid);
        }
        cp_commit();
    }

    // epilogue: bias + (sigmoid), store fp16 -> g_zb / g_hb
    const bool zt = (nt < 8);
    const float* bias = zt ? bz : bh;
    __half* buf = zt ? g_zb : g_hb;
    const int nbase = n0 - (zt ? 0 : 1024);

#pragma unroll
    for (int in = 0; in < 4; in++) {
        const int col = nbase + warp_n * 32 + in * 8 + (lane & 3) * 2;  // even
        const float b0 = __ldg(&bias[col]);
        const float b1 = __ldg(&bias[col + 1]);
#pragma unroll
        for (int im = 0; im < 4; im++) {
            const int row = m0 + warp_m * 64 + im * 16 + (lane >> 2);
            float v0 = acc[im][in][0] + b0;
            float v1 = acc[im][in][1] + b1;
            float v2 = acc[im][in][2] + b0;
            float v3 = acc[im][in][3] + b1;
            if (zt) {
                v0 = 1.0f / (1.0f + __expf(-v0));
                v1 = 1.0f / (1.0f + __expf(-v1));
                v2 = 1.0f / (1.0f + __expf(-v2));
                v3 = 1.0f / (1.0f + __expf(-v3));
            }
            *(__half2*)(buf + (size_t)row * H_DIM + col) =
                __halves2half2(__float2half_rn(v0), __float2half_rn(v1));
            *(__half2*)(buf + (size_t)(row + 8) * H_DIM + col) =
                __halves2half2(__float2half_rn(v2), __float2half_rn(v3));
        }
    }
}

// ---------------- scan: segment summaries then replay ------------------------
// 2 adjacent h-lanes per thread (half2 loads, float2 stores).
__global__ void scan_sum_k() {
    const int idx = blockIdx.x * blockDim.x + threadIdx.x;  // (SEG-1)*8192
    const int seg = idx >> 13;            // 0..14
    const int pr = idx & 8191;
    const int lane0 = pr * 2;
    const int b = lane0 >> 10;
    const int h = lane0 & 1023;
    const size_t base = ((size_t)b * T_DIM + seg * SEGLEN) * H_DIM + h;
    const __half* zp = g_zb + base;
    const __half* hp = g_hb + base;
    float P0 = 1.0f, Q0 = 0.0f, P1 = 1.0f, Q1 = 0.0f;
#pragma unroll 8
    for (int t = 0; t < SEGLEN; t++) {
        const float2 z = __half22float2(*(const __half2*)(zp + (size_t)t * H_DIM));
        const float2 ht = __half22float2(*(const __half2*)(hp + (size_t)t * H_DIM));
        const float a0 = 1.0f - z.x, a1 = 1.0f - z.y;
        P0 *= a0; Q0 = fmaf(a0, Q0, z.x * ht.x);
        P1 *= a1; Q1 = fmaf(a1, Q1, z.y * ht.y);
    }
    *(float2*)&g_P[seg][lane0] = make_float2(P0, P1);
    *(float2*)&g_Q[seg][lane0] = make_float2(Q0, Q1);
}

__global__ void scan_final_k(const float* __restrict__ h0, float* __restrict__ out) {
    const int idx = blockIdx.x * blockDim.x + threadIdx.x;  // SEG*8192
    const int seg = idx >> 13;            // 0..15
    const int pr = idx & 8191;
    const int lane0 = pr * 2;
    const int b = lane0 >> 10;
    const int h = lane0 & 1023;
    float2 hh = *(const float2*)(h0 + lane0);
    for (int s = 0; s < seg; s++) {
        const float2 P = *(const float2*)&g_P[s][lane0];
        const float2 Q = *(const float2*)&g_Q[s][lane0];
        hh.x = fmaf(P.x, hh.x, Q.x);
        hh.y = fmaf(P.y, hh.y, Q.y);
    }
    const size_t base = ((size_t)b * T_DIM + seg * SEGLEN) * H_DIM + h;
    const __half* zp = g_zb + base;
    const __half* hp = g_hb + base;
    float* op = out + base;
#pragma unroll 8
    for (int t = 0; t < SEGLEN; t++) {
        const float2 z = __half22float2(*(const __half2*)(zp + (size_t)t * H_DIM));
        const float2 ht = __half22float2(*(const __half2*)(hp + (size_t)t * H_DIM));
        hh.x = fmaf(z.x, ht.x - hh.x, hh.x);
        hh.y = fmaf(z.y, ht.y - hh.y, hh.y);
        *(float2*)(op + (size_t)t * H_DIM) = hh;
    }
}

// ---------------- launch -----------------------------------------------------
extern "C" void kernel_launch(void* const* d_in, const int* in_sizes, int n_in,
                              void* d_out, int out_size) {
    const float* x  = (const float*)d_in[0];
    const float* h0 = (const float*)d_in[1];
    const float* Wz = (const float*)d_in[2];
    const float* bz = (const float*)d_in[3];
    const float* Wh = (const float*)d_in[4];
    const float* bh = (const float*)d_in[5];
    float* out = (float*)d_out;

    cudaFuncSetAttribute(gemm_k, cudaFuncAttributeMaxDynamicSharedMemorySize, SMEM_TOTAL);

    conv_x_k<<<16384, 256>>>(x);
    conv_w_k<<<1024, 256>>>(Wz, Wh);
    gemm_k<<<dim3(16, 256, 1), 256, SMEM_TOTAL>>>(bz, bh);
    // (SEG-1)*8192/256 = 480 blocks; SEG*8192/256 = 512 blocks
    scan_sum_k<<<480, 256>>>();
    scan_final_k<<<512, 256>>>(h0, out);
}